// round 14
// baseline (speedup 1.0000x reference)
#include <cuda_runtime.h>
#include <cuda_fp16.h>
#include <math.h>

#define GX 128
#define GY 128
#define GZ 128
#define VDIM 28
#define NUM_RAYS 8192
#define NUM_SAMPLES 128
#define NVOX (GX*GY*GZ)
#define NSAMP (NUM_RAYS*NUM_SAMPLES)

#define NBIN 16                    // x-slab bins (xi>>3)
#define CAPBLK 288
#define CAP (CAPBLK*256)           // 73728 records/bin (expected <=65.5k, ~40 sigma)

struct __align__(16) Rec { unsigned int idx, out, xy, zdd; };

// [x][y][z] pair layout: entry v holds fp16 (sigma,r,g,b) of voxel v AND v+1 (+z).
__device__ uint4  g_pairs[NVOX];
__device__ Rec    g_bins[(size_t)NBIN * CAP];
__device__ int    g_cnt[NBIN];
__device__ float4 g_rec2[NSAMP];          // per-sample (att, r, g, b)
__device__ unsigned g_raycnt[NUM_RAYS];   // completed samples per ray

// ---------------------------------------------------------------------------
__device__ __forceinline__ void sh_basis9(const float* __restrict__ ang, float* b) {
    float theta = ang[0], phi = ang[1];
    float st, ct, sp, cp;
    __sincosf(theta, &st, &ct);
    __sincosf(phi, &sp, &cp);
    const float y00 = 0.28209479177387814f;
    const float h3  = 0.4886025119029199f;
    const float q5  = 0.31539156525252005f;
    const float h15 = 1.0925484305920792f;
    const float q15 = 0.5462742152960396f;
    b[0] = y00;
    b[1] = h3 * st * sp;
    b[2] = h3 * ct;
    b[3] = h3 * st * cp;
    b[4] = h15 * st * cp * st * sp;
    b[5] = h15 * st * sp * ct;
    b[6] = q5 * (3.0f * ct * ct - 1.0f);
    b[7] = h15 * st * cp * ct;
    b[8] = q15 * ((st * cp) * (st * cp) - (st * sp) * (st * sp));
}

__device__ __forceinline__ uint2 contract7(const float4* vp, const float* b) {
    float f[VDIM];
    #pragma unroll
    for (int i = 0; i < 7; i++) {
        float4 t = vp[i];
        f[i*4+0] = t.x; f[i*4+1] = t.y; f[i*4+2] = t.z; f[i*4+3] = t.w;
    }
    float r = 0.f, g = 0.f, bl = 0.f;
    #pragma unroll
    for (int k = 0; k < 9; k++) {
        r  = fmaf(f[1  + k], b[k], r);
        g  = fmaf(f[10 + k], b[k], g);
        bl = fmaf(f[19 + k], b[k], bl);
    }
    __half2 h0 = __floats2half2_rn(f[0], r);
    __half2 h1 = __floats2half2_rn(g, bl);
    uint2 u;
    u.x = *(const unsigned int*)&h0;
    u.y = *(const unsigned int*)&h1;
    return u;
}

__device__ __forceinline__ float4 zlerp_pair(uint4 t, float zd) {
    float2 a0 = __half22float2(*(__half2*)&t.x);
    float2 a1 = __half22float2(*(__half2*)&t.y);
    float2 b0 = __half22float2(*(__half2*)&t.z);
    float2 b1 = __half22float2(*(__half2*)&t.w);
    return make_float4(fmaf(b0.x - a0.x, zd, a0.x),
                       fmaf(b0.y - a0.y, zd, a0.y),
                       fmaf(b1.x - a1.x, zd, a1.x),
                       fmaf(b1.y - a1.y, zd, a1.y));
}

__device__ __forceinline__ float4 f4lerp(float4 a, float4 b, float t) {
    return make_float4(fmaf(b.x - a.x, t, a.x),
                       fmaf(b.y - a.y, t, a.y),
                       fmaf(b.z - a.z, t, a.z),
                       fmaf(b.w - a.w, t, a.w));
}

// ---------------------------------------------------------------------------
// Reset counters (graph-replay safe). 32x256 threads cover 8192 ray counters.
// ---------------------------------------------------------------------------
__global__ __launch_bounds__(256) void zero_kernel() {
    int i = blockIdx.x * 256 + threadIdx.x;
    g_raycnt[i] = 0;
    if (i < NBIN) g_cnt[i] = 0;
}

// ---------------------------------------------------------------------------
// Bin kernel (R8-proven): 1024 samples/block, smem-staged scatter to 16 bins.
// ---------------------------------------------------------------------------
__global__ __launch_bounds__(256) void bin_kernel(
    const float* __restrict__ pos, const float* __restrict__ dist)
{
    __shared__ int scnt[NBIN];
    __shared__ int sbase[NBIN];
    __shared__ int soff[NBIN];
    __shared__ Rec srec[1024];

    int t = threadIdx.x;
    if (t < NBIN) scnt[t] = 0;
    __syncthreads();

    int base = blockIdx.x * 1024;
    Rec r[4]; int ck[4]; int slot[4];
    #pragma unroll
    for (int k = 0; k < 4; k++) {
        int i = base + k*256 + t;
        const float* p = pos + (size_t)i * 3;
        float x = p[0], y = p[1], z = p[2];
        float d = dist[i];
        int xi = (int)x, yi = (int)y, zi = (int)z;   // in [0,125]
        __half2 hxy = __floats2half2_rn(x - (float)xi, y - (float)yi);
        __half2 hzd = __floats2half2_rn(z - (float)zi, d);
        r[k].idx = (xi << 14) | (yi << 7) | zi;
        r[k].out = (unsigned)i;
        r[k].xy  = *(unsigned int*)&hxy;
        r[k].zdd = *(unsigned int*)&hzd;
        ck[k] = xi >> 3;
        slot[k] = atomicAdd(&scnt[ck[k]], 1);
    }
    __syncthreads();
    if (t == 0) {
        int run = 0;
        #pragma unroll
        for (int c = 0; c < NBIN; c++) { soff[c] = run; run += scnt[c]; }
    }
    if (t < NBIN) sbase[t] = atomicAdd(&g_cnt[t], scnt[t]);
    __syncthreads();
    #pragma unroll
    for (int k = 0; k < 4; k++) srec[soff[ck[k]] + slot[k]] = r[k];
    __syncthreads();

    for (int k = t; k < 1024; k += 256) {
        int c = 0;
        #pragma unroll
        for (int j = 1; j < NBIN; j++) if (k >= soff[j]) c = j;
        int gpos = sbase[c] + (k - soff[c]);
        if (gpos < CAP) g_bins[(size_t)c * CAP + gpos] = srec[k];
    }
}

// ---------------------------------------------------------------------------
// Kernel: reduce (R12 champion form — smem-staged flat coalesced reads).
// ---------------------------------------------------------------------------
__global__ __launch_bounds__(256) void reduce_kernel(
    const float* __restrict__ grid, const float* __restrict__ ang)
{
    __shared__ float4 sraw[7 * 256];
    __shared__ uint2  sres[257];

    float b[9];
    sh_basis9(ang, b);

    int t = threadIdx.x;
    size_t base4 = (size_t)blockIdx.x * (7 * 256);
    const float4* gp = (const float4*)grid;

    #pragma unroll
    for (int k = 0; k < 7; k++) {
        int g = k * 256 + t;
        sraw[g] = __ldcs(gp + base4 + g);
    }
    int vbase = blockIdx.x * 256;
    if (t == 0) {
        int v2 = vbase + 256;
        if (v2 >= NVOX) v2 = NVOX - 1;               // value never read
        sres[256] = contract7((const float4*)(grid + (size_t)v2 * VDIM), b);
    }
    __syncthreads();
    sres[t] = contract7(&sraw[t * 7], b);
    __syncthreads();
    uint2 a = sres[t], c = sres[t + 1];
    g_pairs[vbase + t] = make_uint4(a.x, a.y, c.x, c.y);
}

// ---------------------------------------------------------------------------
// Render: bin-ordered gathers (slab locality) + fused per-ray finalize.
// Block -> (bin, 256 records). Blocks dispatch in bin order, so concurrent
// gathers are confined to a few 2.25 MB grid slabs -> sequentialized DRAM
// fetch + L2 reuse. Last sample of a ray performs the serial scan.
// ---------------------------------------------------------------------------
__global__ __launch_bounds__(256) void render_kernel(float* __restrict__ out)
{
    int bin = blockIdx.x / CAPBLK;
    int rb  = blockIdx.x % CAPBLK;
    int j   = rb * 256 + threadIdx.x;
    int cnt = g_cnt[bin]; if (cnt > CAP) cnt = CAP;
    if (j >= cnt) return;

    Rec r = g_bins[(size_t)bin * CAP + j];
    float2 xy  = __half22float2(*(__half2*)&r.xy);
    float2 zdd = __half22float2(*(__half2*)&r.zdd);
    int e = (int)r.idx;
    const uint4* __restrict__ G = g_pairs;
    uint4 t00 = __ldcg(G + e);                   // (x0,y0)
    uint4 t01 = __ldcg(G + e + 128);             // (x0,y1)
    uint4 t10 = __ldcg(G + e + 16384);           // (x1,y0)
    uint4 t11 = __ldcg(G + e + 16384 + 128);     // (x1,y1)
    float4 v00 = zlerp_pair(t00, zdd.x);
    float4 v01 = zlerp_pair(t01, zdd.x);
    float4 v10 = zlerp_pair(t10, zdd.x);
    float4 v11 = zlerp_pair(t11, zdd.x);
    float4 v0 = f4lerp(v00, v10, xy.x);
    float4 v1 = f4lerp(v01, v11, xy.x);
    float4 v  = f4lerp(v0, v1, xy.y);
    float att = __expf(-v.x * zdd.y);

    int ray = (int)(r.out >> 7);
    g_rec2[r.out] = make_float4(att, v.y, v.z, v.w);

    // Publish, then count. Completing thread (old==127) finalizes the ray.
    __threadfence();
    unsigned old = atomicAdd(&g_raycnt[ray], 1u);
    if (old == NUM_SAMPLES - 1) {
        __threadfence();
        const float4* rr = &g_rec2[(size_t)ray * NUM_SAMPLES];
        float T = 0.f, ar = 0.f, ag = 0.f, ab = 0.f;
        #pragma unroll 4
        for (int s = 0; s < NUM_SAMPLES; s++) {
            float4 q = __ldcg(rr + s);
            T += q.x;
            float w = T * (1.0f - q.x);
            ar = fmaf(w, q.y, ar);
            ag = fmaf(w, q.z, ag);
            ab = fmaf(w, q.w, ab);
        }
        out[ray * 3 + 0] = ar;
        out[ray * 3 + 1] = ag;
        out[ray * 3 + 2] = ab;
    }
}

extern "C" void kernel_launch(void* const* d_in, const int* in_sizes, int n_in,
                              void* d_out, int out_size) {
    const float* voxel_grid = (const float*)d_in[0];
    const float* sample_positions = (const float*)d_in[1];
    const float* sample_distances = (const float*)d_in[2];
    const float* viewing_angle = (const float*)d_in[3];
    float* out = (float*)d_out;

    zero_kernel<<<NUM_RAYS / 256, 256>>>();
    bin_kernel<<<NSAMP / 1024, 256>>>(sample_positions, sample_distances);
    reduce_kernel<<<NVOX / 256, 256>>>(voxel_grid, viewing_angle);
    render_kernel<<<NBIN * CAPBLK, 256>>>(out);
}

// round 15
// speedup vs baseline: 1.6845x; 1.6845x over previous
#include <cuda_runtime.h>
#include <cuda_fp16.h>
#include <math.h>

#define GX 128
#define GY 128
#define GZ 128
#define VDIM 28
#define NUM_RAYS 8192
#define NUM_SAMPLES 128
#define NVOX (GX*GY*GZ)
#define NSAMP (NUM_RAYS*NUM_SAMPLES)

#define NBIN 16                    // x-slab bins (xi>>3)
#define CAPBLK 288
#define CAP (CAPBLK*256)           // 73728 records/bin (expected <=65.5k, ~40 sigma)

struct __align__(16) Rec { unsigned int idx, out, xy, zdd; };

// [x][y][z] pair layout: entry v holds fp16 (sigma,r,g,b) of voxel v AND v+1 (+z).
__device__ uint4  g_pairs[NVOX];
__device__ Rec    g_bins[(size_t)NBIN * CAP];
__device__ int    g_cnt[NBIN];
__device__ uint2  g_rec2[NSAMP];   // per-sample fp16 (att, r | g, b) — 8 B

// ---------------------------------------------------------------------------
__device__ __forceinline__ void sh_basis9(const float* __restrict__ ang, float* b) {
    float theta = ang[0], phi = ang[1];
    float st, ct, sp, cp;
    __sincosf(theta, &st, &ct);
    __sincosf(phi, &sp, &cp);
    const float y00 = 0.28209479177387814f;
    const float h3  = 0.4886025119029199f;
    const float q5  = 0.31539156525252005f;
    const float h15 = 1.0925484305920792f;
    const float q15 = 0.5462742152960396f;
    b[0] = y00;
    b[1] = h3 * st * sp;
    b[2] = h3 * ct;
    b[3] = h3 * st * cp;
    b[4] = h15 * st * cp * st * sp;
    b[5] = h15 * st * sp * ct;
    b[6] = q5 * (3.0f * ct * ct - 1.0f);
    b[7] = h15 * st * cp * ct;
    b[8] = q15 * ((st * cp) * (st * cp) - (st * sp) * (st * sp));
}

__device__ __forceinline__ uint2 contract7(const float4* vp, const float* b) {
    float f[VDIM];
    #pragma unroll
    for (int i = 0; i < 7; i++) {
        float4 t = vp[i];
        f[i*4+0] = t.x; f[i*4+1] = t.y; f[i*4+2] = t.z; f[i*4+3] = t.w;
    }
    float r = 0.f, g = 0.f, bl = 0.f;
    #pragma unroll
    for (int k = 0; k < 9; k++) {
        r  = fmaf(f[1  + k], b[k], r);
        g  = fmaf(f[10 + k], b[k], g);
        bl = fmaf(f[19 + k], b[k], bl);
    }
    __half2 h0 = __floats2half2_rn(f[0], r);
    __half2 h1 = __floats2half2_rn(g, bl);
    uint2 u;
    u.x = *(const unsigned int*)&h0;
    u.y = *(const unsigned int*)&h1;
    return u;
}

__device__ __forceinline__ float4 zlerp_pair(uint4 t, float zd) {
    float2 a0 = __half22float2(*(__half2*)&t.x);
    float2 a1 = __half22float2(*(__half2*)&t.y);
    float2 b0 = __half22float2(*(__half2*)&t.z);
    float2 b1 = __half22float2(*(__half2*)&t.w);
    return make_float4(fmaf(b0.x - a0.x, zd, a0.x),
                       fmaf(b0.y - a0.y, zd, a0.y),
                       fmaf(b1.x - a1.x, zd, a1.x),
                       fmaf(b1.y - a1.y, zd, a1.y));
}

__device__ __forceinline__ float4 f4lerp(float4 a, float4 b, float t) {
    return make_float4(fmaf(b.x - a.x, t, a.x),
                       fmaf(b.y - a.y, t, a.y),
                       fmaf(b.z - a.z, t, a.z),
                       fmaf(b.w - a.w, t, a.w));
}

// ---------------------------------------------------------------------------
__global__ void zero_kernel() {
    if (threadIdx.x < NBIN) g_cnt[threadIdx.x] = 0;
}

// ---------------------------------------------------------------------------
// Bin kernel (proven): 1024 samples/block, smem-staged scatter to 16 bins.
// ---------------------------------------------------------------------------
__global__ __launch_bounds__(256) void bin_kernel(
    const float* __restrict__ pos, const float* __restrict__ dist)
{
    __shared__ int scnt[NBIN];
    __shared__ int sbase[NBIN];
    __shared__ int soff[NBIN];
    __shared__ Rec srec[1024];

    int t = threadIdx.x;
    if (t < NBIN) scnt[t] = 0;
    __syncthreads();

    int base = blockIdx.x * 1024;
    Rec r[4]; int ck[4]; int slot[4];
    #pragma unroll
    for (int k = 0; k < 4; k++) {
        int i = base + k*256 + t;
        const float* p = pos + (size_t)i * 3;
        float x = p[0], y = p[1], z = p[2];
        float d = dist[i];
        int xi = (int)x, yi = (int)y, zi = (int)z;   // in [0,125]
        __half2 hxy = __floats2half2_rn(x - (float)xi, y - (float)yi);
        __half2 hzd = __floats2half2_rn(z - (float)zi, d);
        r[k].idx = (xi << 14) | (yi << 7) | zi;
        r[k].out = (unsigned)i;
        r[k].xy  = *(unsigned int*)&hxy;
        r[k].zdd = *(unsigned int*)&hzd;
        ck[k] = xi >> 3;
        slot[k] = atomicAdd(&scnt[ck[k]], 1);
    }
    __syncthreads();
    if (t == 0) {
        int run = 0;
        #pragma unroll
        for (int c = 0; c < NBIN; c++) { soff[c] = run; run += scnt[c]; }
    }
    if (t < NBIN) sbase[t] = atomicAdd(&g_cnt[t], scnt[t]);
    __syncthreads();
    #pragma unroll
    for (int k = 0; k < 4; k++) srec[soff[ck[k]] + slot[k]] = r[k];
    __syncthreads();

    for (int k = t; k < 1024; k += 256) {
        int c = 0;
        #pragma unroll
        for (int j = 1; j < NBIN; j++) if (k >= soff[j]) c = j;
        int gpos = sbase[c] + (k - soff[c]);
        if (gpos < CAP) g_bins[(size_t)c * CAP + gpos] = srec[k];
    }
}

// ---------------------------------------------------------------------------
// Reduce (R12 champion form — smem-staged flat coalesced reads).
// ---------------------------------------------------------------------------
__global__ __launch_bounds__(256) void reduce_kernel(
    const float* __restrict__ grid, const float* __restrict__ ang)
{
    __shared__ float4 sraw[7 * 256];
    __shared__ uint2  sres[257];

    float b[9];
    sh_basis9(ang, b);

    int t = threadIdx.x;
    size_t base4 = (size_t)blockIdx.x * (7 * 256);
    const float4* gp = (const float4*)grid;

    #pragma unroll
    for (int k = 0; k < 7; k++) {
        int g = k * 256 + t;
        sraw[g] = __ldcs(gp + base4 + g);
    }
    int vbase = blockIdx.x * 256;
    if (t == 0) {
        int v2 = vbase + 256;
        if (v2 >= NVOX) v2 = NVOX - 1;               // value never read
        sres[256] = contract7((const float4*)(grid + (size_t)v2 * VDIM), b);
    }
    __syncthreads();
    sres[t] = contract7(&sraw[t * 7], b);
    __syncthreads();
    uint2 a = sres[t], c = sres[t + 1];
    g_pairs[vbase + t] = make_uint4(a.x, a.y, c.x, c.y);
}

// ---------------------------------------------------------------------------
// Render: bin-ordered gathers (slab-sequential DRAM fetch + L2 reuse).
// Pure dataflow: no atomics, no fences. Writes 8 B fp16 record per sample.
// ---------------------------------------------------------------------------
__global__ __launch_bounds__(256) void render_kernel()
{
    int bin = blockIdx.x / CAPBLK;
    int rb  = blockIdx.x % CAPBLK;
    int j   = rb * 256 + threadIdx.x;
    int cnt = g_cnt[bin]; if (cnt > CAP) cnt = CAP;
    if (j >= cnt) return;

    Rec r = g_bins[(size_t)bin * CAP + j];
    float2 xy  = __half22float2(*(__half2*)&r.xy);
    float2 zdd = __half22float2(*(__half2*)&r.zdd);
    int e = (int)r.idx;
    const uint4* __restrict__ G = g_pairs;
    uint4 t00 = __ldcg(G + e);                   // (x0,y0)
    uint4 t01 = __ldcg(G + e + 128);             // (x0,y1)
    uint4 t10 = __ldcg(G + e + 16384);           // (x1,y0)
    uint4 t11 = __ldcg(G + e + 16384 + 128);     // (x1,y1)
    float4 v00 = zlerp_pair(t00, zdd.x);
    float4 v01 = zlerp_pair(t01, zdd.x);
    float4 v10 = zlerp_pair(t10, zdd.x);
    float4 v11 = zlerp_pair(t11, zdd.x);
    float4 v0 = f4lerp(v00, v10, xy.x);
    float4 v1 = f4lerp(v01, v11, xy.x);
    float4 v  = f4lerp(v0, v1, xy.y);
    float att = __expf(-v.x * zdd.y);

    __half2 h0 = __floats2half2_rn(att, v.y);
    __half2 h1 = __floats2half2_rn(v.z, v.w);
    uint2 u;
    u.x = *(const unsigned int*)&h0;
    u.y = *(const unsigned int*)&h1;
    g_rec2[r.out] = u;
}

// ---------------------------------------------------------------------------
// Finalize: per-ray scan of att, weight, rgb sum. 2 rays per 256-thread block
// (R12-proven scan structure), coalesced 8 B reads.
// ---------------------------------------------------------------------------
__global__ __launch_bounds__(256) void finalize_kernel(float* __restrict__ out)
{
    __shared__ float s_wsum[8];
    __shared__ float s_acc[8][3];

    int tid  = threadIdx.x;
    int wid  = tid >> 5;
    int lane = tid & 31;
    int wir  = wid & 3;
    int rbase = wid & 4;
    int ray  = blockIdx.x * 2 + (tid >> 7);
    int s    = tid & 127;

    uint2 u = __ldcs(&g_rec2[(size_t)ray * NUM_SAMPLES + s]);
    float2 f0 = __half22float2(*(__half2*)&u.x);   // att, r
    float2 f1 = __half22float2(*(__half2*)&u.y);   // g, b
    float att = f0.x;

    float inc = att;
    #pragma unroll
    for (int o = 1; o < 32; o <<= 1) {
        float n = __shfl_up_sync(0xffffffffu, inc, o);
        if (lane >= o) inc += n;
    }
    if (lane == 31) s_wsum[wid] = inc;
    __syncthreads();
    float off = 0.f;
    #pragma unroll
    for (int w = 0; w < 3; w++)
        if (w < wir) off += s_wsum[rbase + w];
    float T = inc + off;

    float w = T * (1.0f - att);
    float ar = w * f0.y, ag = w * f1.x, ab = w * f1.y;

    #pragma unroll
    for (int o = 16; o > 0; o >>= 1) {
        ar += __shfl_xor_sync(0xffffffffu, ar, o);
        ag += __shfl_xor_sync(0xffffffffu, ag, o);
        ab += __shfl_xor_sync(0xffffffffu, ab, o);
    }
    if (lane == 0) {
        s_acc[wid][0] = ar;
        s_acc[wid][1] = ag;
        s_acc[wid][2] = ab;
    }
    __syncthreads();
    if (wir == 0 && lane < 3) {
        float v = s_acc[rbase + 0][lane] + s_acc[rbase + 1][lane]
                + s_acc[rbase + 2][lane] + s_acc[rbase + 3][lane];
        out[ray * 3 + lane] = v;
    }
}

extern "C" void kernel_launch(void* const* d_in, const int* in_sizes, int n_in,
                              void* d_out, int out_size) {
    const float* voxel_grid = (const float*)d_in[0];
    const float* sample_positions = (const float*)d_in[1];
    const float* sample_distances = (const float*)d_in[2];
    const float* viewing_angle = (const float*)d_in[3];
    float* out = (float*)d_out;

    zero_kernel<<<1, 32>>>();
    bin_kernel<<<NSAMP / 1024, 256>>>(sample_positions, sample_distances);
    reduce_kernel<<<NVOX / 256, 256>>>(voxel_grid, viewing_angle);
    render_kernel<<<NBIN * CAPBLK, 256>>>();
    finalize_kernel<<<NUM_RAYS / 2, 256>>>(out);
}

// round 16
// speedup vs baseline: 2.1380x; 1.2692x over previous
#include <cuda_runtime.h>
#include <cuda_fp16.h>
#include <math.h>

#define GX 128
#define GY 128
#define GZ 128
#define VDIM 28
#define NUM_RAYS 8192
#define NUM_SAMPLES 128
#define NVOX (GX*GY*GZ)

// Reduced grid: 8 B per voxel, fp16 (sigma, r | g, b), [x][y][z] layout.
// 16 MB -> half the random DRAM fetch of the 32 MB pair grid.
__device__ uint2 g_vox[NVOX];

// ---------------------------------------------------------------------------
// SH basis (degree 2), reference coefficient order.
// ---------------------------------------------------------------------------
__device__ __forceinline__ void sh_basis9(const float* __restrict__ ang, float* b) {
    float theta = ang[0], phi = ang[1];
    float st, ct, sp, cp;
    __sincosf(theta, &st, &ct);
    __sincosf(phi, &sp, &cp);
    const float y00 = 0.28209479177387814f;
    const float h3  = 0.4886025119029199f;
    const float q5  = 0.31539156525252005f;
    const float h15 = 1.0925484305920792f;
    const float q15 = 0.5462742152960396f;
    b[0] = y00;
    b[1] = h3 * st * sp;
    b[2] = h3 * ct;
    b[3] = h3 * st * cp;
    b[4] = h15 * st * cp * st * sp;
    b[5] = h15 * st * sp * ct;
    b[6] = q5 * (3.0f * ct * ct - 1.0f);
    b[7] = h15 * st * cp * ct;
    b[8] = q15 * ((st * cp) * (st * cp) - (st * sp) * (st * sp));
}

__device__ __forceinline__ uint2 contract7(const float4* vp, const float* b) {
    float f[VDIM];
    #pragma unroll
    for (int i = 0; i < 7; i++) {
        float4 t = vp[i];
        f[i*4+0] = t.x; f[i*4+1] = t.y; f[i*4+2] = t.z; f[i*4+3] = t.w;
    }
    float r = 0.f, g = 0.f, bl = 0.f;
    #pragma unroll
    for (int k = 0; k < 9; k++) {
        r  = fmaf(f[1  + k], b[k], r);
        g  = fmaf(f[10 + k], b[k], g);
        bl = fmaf(f[19 + k], b[k], bl);
    }
    __half2 h0 = __floats2half2_rn(f[0], r);
    __half2 h1 = __floats2half2_rn(g, bl);
    uint2 u;
    u.x = *(const unsigned int*)&h0;
    u.y = *(const unsigned int*)&h1;
    return u;
}

// ---------------------------------------------------------------------------
// Kernel 1: contract 28 features -> 8 B voxel. R12's smem-staged flat
// coalesced reads (proven at DRAM roofline); no pairing, no halo.
// ---------------------------------------------------------------------------
__global__ __launch_bounds__(256) void reduce_kernel(
    const float* __restrict__ grid, const float* __restrict__ ang)
{
    __shared__ float4 sraw[7 * 256];

    float b[9];
    sh_basis9(ang, b);

    int t = threadIdx.x;
    size_t base4 = (size_t)blockIdx.x * (7 * 256);
    const float4* gp = (const float4*)grid;

    #pragma unroll
    for (int k = 0; k < 7; k++) {
        int g = k * 256 + t;
        sraw[g] = __ldcs(gp + base4 + g);   // contiguous, evict-first
    }
    __syncthreads();

    g_vox[blockIdx.x * 256 + t] = contract7(&sraw[t * 7], b);
}

// ---------------------------------------------------------------------------
// Kernel 2: rendering. 2 lanes per sample (lane parity = z-corner),
// 16 samples per warp, 8 warps = 1 ray per 256-thread block. (R5 machinery,
// z-pairing on the native fast axis -> buddy-lane loads coalesce to 16B.)
// ---------------------------------------------------------------------------
__device__ __forceinline__ float4 unpack8(uint2 u) {
    float2 a = __half22float2(*(__half2*)&u.x);   // sigma, r
    float2 b = __half22float2(*(__half2*)&u.y);   // g, b
    return make_float4(a.x, a.y, b.x, b.y);
}

__device__ __forceinline__ float4 f4lerp(float4 a, float4 b, float t) {
    return make_float4(fmaf(b.x - a.x, t, a.x),
                       fmaf(b.y - a.y, t, a.y),
                       fmaf(b.z - a.z, t, a.z),
                       fmaf(b.w - a.w, t, a.w));
}

// z-lerp across the lane pair; both lanes end with the full sample value.
__device__ __forceinline__ float zlerp1(float mine, int lz, float zd) {
    float oth = __shfl_xor_sync(0xffffffffu, mine, 1);
    float a = lz ? oth : mine;   // z0 value
    float b = lz ? mine : oth;   // z1 value
    return fmaf(b - a, zd, a);
}

__global__ __launch_bounds__(256) void render_kernel(
    const float* __restrict__ pos, const float* __restrict__ dist,
    float* __restrict__ out)
{
    __shared__ float s_wsum[8];
    __shared__ float s_acc[8][3];

    int ray  = blockIdx.x;
    int tid  = threadIdx.x;
    int wid  = tid >> 5;
    int lane = tid & 31;
    int p    = lane >> 1;         // sample within warp: 0..15
    int lz   = lane & 1;          // which z-corner this lane owns
    int s    = (wid << 4) + p;    // sample within ray: 0..127

    const float* pp = pos + (size_t)ray * (NUM_SAMPLES * 3) + s * 3;
    float x = pp[0], y = pp[1], z = pp[2];
    float d = dist[(size_t)ray * NUM_SAMPLES + s];

    int xi = (int)x, yi = (int)y, zi = (int)z;   // in [0,125]
    float xd = x - (float)xi, yd = y - (float)yi, zd = z - (float)zi;

    // 4 xy-corner voxels at this lane's z-plane; buddy lane covers z+1.
    int e = (xi << 14) + (yi << 7) + zi + lz;
    const uint2* __restrict__ G = g_vox;
    uint2 u00 = __ldcg(G + e);                 // (x0,y0)
    uint2 u01 = __ldcg(G + e + GZ);            // (x0,y1)
    uint2 u10 = __ldcg(G + e + GY*GZ);         // (x1,y0)
    uint2 u11 = __ldcg(G + e + GY*GZ + GZ);    // (x1,y1)
    float4 c00 = unpack8(u00), c01 = unpack8(u01);
    float4 c10 = unpack8(u10), c11 = unpack8(u11);
    float4 c0 = f4lerp(c00, c10, xd);
    float4 c1 = f4lerp(c01, c11, xd);
    float4 v  = f4lerp(c0, c1, yd);            // xy-bilerp at this z-plane

    // z-lerp across the lane pair.
    float sig = zlerp1(v.x, lz, zd);
    float rr  = zlerp1(v.y, lz, zd);
    float gg  = zlerp1(v.z, lz, zd);
    float bb  = zlerp1(v.w, lz, zd);

    float att = __expf(-sig * d);

    // Inclusive cumsum of att over the ray (R5-proven compact scan:
    // samples duplicated in lane pairs; compact to 16-lane groups, scan).
    float att_s = __shfl_sync(0xffffffffu, att, (lane & 15) << 1);
    float inc = att_s;
    #pragma unroll
    for (int o = 1; o < 16; o <<= 1) {
        float n = __shfl_up_sync(0xffffffffu, inc, o);
        if ((lane & 15) >= o) inc += n;
    }
    float inc_mine = __shfl_sync(0xffffffffu, inc, p);
    float wtot     = __shfl_sync(0xffffffffu, inc, 15);
    if (lane == 0) s_wsum[wid] = wtot;
    __syncthreads();
    float off = 0.f;
    #pragma unroll
    for (int w = 0; w < 7; w++)
        if (w < wid) off += s_wsum[w];
    float T = off + inc_mine;

    float w = T * (1.0f - att);
    float ar = w * rr, ag = w * gg, ab = w * bb;

    #pragma unroll
    for (int o = 16; o > 0; o >>= 1) {
        ar += __shfl_xor_sync(0xffffffffu, ar, o);
        ag += __shfl_xor_sync(0xffffffffu, ag, o);
        ab += __shfl_xor_sync(0xffffffffu, ab, o);
    }
    if (lane == 0) {               // each sample counted twice -> x0.5 (exact)
        s_acc[wid][0] = 0.5f * ar;
        s_acc[wid][1] = 0.5f * ag;
        s_acc[wid][2] = 0.5f * ab;
    }
    __syncthreads();
    if (tid < 3) {
        float acc = 0.f;
        #pragma unroll
        for (int wv = 0; wv < 8; wv++) acc += s_acc[wv][tid];
        out[ray * 3 + tid] = acc;
    }
}

extern "C" void kernel_launch(void* const* d_in, const int* in_sizes, int n_in,
                              void* d_out, int out_size) {
    const float* voxel_grid = (const float*)d_in[0];
    const float* sample_positions = (const float*)d_in[1];
    const float* sample_distances = (const float*)d_in[2];
    const float* viewing_angle = (const float*)d_in[3];
    float* out = (float*)d_out;

    reduce_kernel<<<NVOX / 256, 256>>>(voxel_grid, viewing_angle);
    render_kernel<<<NUM_RAYS, 256>>>(sample_positions, sample_distances, out);
}